// round 15
// baseline (speedup 1.0000x reference)
#include <cuda_runtime.h>
#include <cstdint>

// FFM forward: out[b] = sigmoid( relu(sum_i feats[i]*Wd[i] + bd) + fm[b] )
// fm[b] = sum over 15 field pairs (i<j) of dot( mean_k E_i[j-1][x_i[b,k]],
//                                               mean_k E_j[i  ][x_j[b,k]] )
// Shapes: x_i (B,S_i) i32; E_i (5,D_i,16) f32; L_i (D_i,1) f32; Wd (6,1); bd (1,).
// B=16384, S={1,1,50,20,1,1}, D={1e6,5e5,5e5,1e5,1e4,1e3}.
// Inputs interleaved: x0..x5, E0,L0,E1,L1,...,E5,L5, Wd, bd (detected at launch).
//
// L2 policy (L2-ONLY; L1 untouched). L2 persists across graph replays, so:
//   E2 rows in first 64MB of table -> L2::evict_last  (pinned across replays)
//   E2 remaining rows              -> L2::evict_first (streaming)
//   E3 (32MB table)                -> L2::evict_last  (resident)
//   E0/E1 singletons               -> L2::evict_first (tiny, no reuse)
// Pinned total ~96MB of 126MB L2.

#define NIDX 74
#define E2_PIN_ROWS (1 << 20)   // 1M rows x 64B = 64MB of the 160MB E2 table

__device__ __forceinline__ float4 ldg_v4_policy(const float4* p, uint64_t pol) {
    float4 v;
    asm volatile("ld.global.nc.L2::cache_hint.v4.f32 {%0,%1,%2,%3}, [%4], %5;"
                 : "=f"(v.x), "=f"(v.y), "=f"(v.z), "=f"(v.w)
                 : "l"(p), "l"(pol));
    return v;
}

// ---------------- fast kernel: float4 gathers + L2 residency management ----------------
__global__ __launch_bounds__(96) void ffm_kernel_v8(
    const int* __restrict__ x0, const int* __restrict__ x1,
    const int* __restrict__ x2, const int* __restrict__ x3,
    const int* __restrict__ x4, const int* __restrict__ x5,
    const float* __restrict__ E0, const float* __restrict__ E1,
    const float* __restrict__ E2, const float* __restrict__ E3,
    const float* __restrict__ E4, const float* __restrict__ E5,
    const float* __restrict__ L0, const float* __restrict__ L1,
    const float* __restrict__ L2t, const float* __restrict__ L3,
    const float* __restrict__ L4, const float* __restrict__ L5,
    const float* __restrict__ Wd, const float* __restrict__ bd,
    float* __restrict__ out)
{
    __shared__ __align__(16) float V[30][16];  // (feature*5 + slot, latent)
    __shared__ int   sidx[NIDX];   // [0]=x0 [1]=x1 [2..51]=x2 [52..71]=x3 [72]=x4 [73]=x5
    __shared__ float sfeat[6];

    const int b   = blockIdx.x;
    const int tid = threadIdx.x;

    // ---- load indices into smem ----
    if (tid < 50)                  sidx[2  + tid]        = x2[b * 50 + tid];
    else if (tid < 70)             sidx[52 + (tid - 50)] = x3[b * 20 + (tid - 50)];
    else if (tid == 70)            sidx[0]  = x0[b];
    else if (tid == 71)            sidx[1]  = x1[b];
    else if (tid == 72)            sidx[72] = x4[b];
    else if (tid == 73)            sidx[73] = x5[b];
    __syncthreads();

    // ---- gather: 80 threads = (slot s 0..4) x (quad q 0..3) x (ksub 0..3) ----
    if (tid < 80) {
        const int s    = tid >> 4;        // slot
        const int q    = (tid >> 2) & 3;  // float4 quad within row
        const int ksub = tid & 3;         // k-parallel split / singleton select
        const unsigned mask = (tid < 64) ? 0xFFFFFFFFu : 0x0000FFFFu;

        uint64_t pol_first, pol_last;
        asm volatile("createpolicy.fractional.L2::evict_first.b64 %0, 1.0;" : "=l"(pol_first));
        asm volatile("createpolicy.fractional.L2::evict_last.b64  %0, 1.0;" : "=l"(pol_last));

        // feature 2: 50 indices split 4 ways.
        // Address-split policy: first 64MB of table pinned (evict_last, stays
        // in L2 across graph replays), rest streamed (evict_first).
        float4 a2 = make_float4(0.f, 0.f, 0.f, 0.f);
        #pragma unroll
        for (int k = ksub; k < 50; k += 4) {
            const int row = s * 500000 + sidx[2 + k];
            const uint64_t pol = (row < E2_PIN_ROWS) ? pol_last : pol_first;
            const float4 v = ldg_v4_policy((const float4*)E2 + (long)row * 4 + q, pol);
            a2.x += v.x; a2.y += v.y; a2.z += v.z; a2.w += v.w;
        }

        // feature 3: 20 indices split 4 ways; L2 evict-last (32MB resident)
        float4 a3 = make_float4(0.f, 0.f, 0.f, 0.f);
        #pragma unroll
        for (int k = ksub; k < 20; k += 4) {
            const int row = s * 100000 + sidx[52 + k];
            const float4 v = ldg_v4_policy((const float4*)E3 + (long)row * 4 + q, pol_last);
            a3.x += v.x; a3.y += v.y; a3.z += v.z; a3.w += v.w;
        }

        // singleton features: ksub 0->E0, 1->E1 (evict-first), 2->E4, 3->E5 (default)
        {
            float4 v;
            int frow;
            if (ksub == 0) {
                v = ldg_v4_policy((const float4*)E0 + (long)(s * 1000000 + sidx[0]) * 4 + q, pol_first);
                frow = 0 * 5 + s;
            } else if (ksub == 1) {
                v = ldg_v4_policy((const float4*)E1 + (long)(s * 500000 + sidx[1]) * 4 + q, pol_first);
                frow = 1 * 5 + s;
            } else if (ksub == 2) {
                v = __ldg((const float4*)E4 + (long)(s * 10000 + sidx[72]) * 4 + q);
                frow = 4 * 5 + s;
            } else {
                v = __ldg((const float4*)E5 + (long)(s * 1000 + sidx[73]) * 4 + q);
                frow = 5 * 5 + s;
            }
            ((float4*)&V[frow][0])[q] = v;
        }

        // reduce seq partials across the 4 ksub lanes
        #pragma unroll
        for (int o = 1; o <= 2; o <<= 1) {
            a2.x += __shfl_xor_sync(mask, a2.x, o);
            a2.y += __shfl_xor_sync(mask, a2.y, o);
            a2.z += __shfl_xor_sync(mask, a2.z, o);
            a2.w += __shfl_xor_sync(mask, a2.w, o);
            a3.x += __shfl_xor_sync(mask, a3.x, o);
            a3.y += __shfl_xor_sync(mask, a3.y, o);
            a3.z += __shfl_xor_sync(mask, a3.z, o);
            a3.w += __shfl_xor_sync(mask, a3.w, o);
        }
        if (ksub == 0) {
            const float i50 = 1.0f / 50.0f, i20 = 1.0f / 20.0f;
            ((float4*)&V[2 * 5 + s][0])[q] =
                make_float4(a2.x * i50, a2.y * i50, a2.z * i50, a2.w * i50);
            ((float4*)&V[3 * 5 + s][0])[q] =
                make_float4(a3.x * i20, a3.y * i20, a3.z * i20, a3.w * i20);
        }
    } else if (tid < 86) {
        // ---- linear features (small tables, default policy) ----
        const int i = tid - 80;
        float f = 0.f;
        switch (i) {
            case 0: f = L0[sidx[0]];  break;
            case 1: f = L1[sidx[1]];  break;
            case 2: {
                float a = 0.f;
                #pragma unroll
                for (int k = 0; k < 50; k++) a += L2t[sidx[2 + k]];
                f = a * (1.0f / 50.0f);
            } break;
            case 3: {
                float a = 0.f;
                #pragma unroll
                for (int k = 0; k < 20; k++) a += L3[sidx[52 + k]];
                f = a * (1.0f / 20.0f);
            } break;
            case 4: f = L4[sidx[72]]; break;
            case 5: f = L5[sidx[73]]; break;
        }
        sfeat[i] = f;
    }
    __syncthreads();

    // ---- fm: 15 disjoint pair dot-products over 16 lanes each ----
    if (tid < 32) {
        static const signed char rowA[15] =
            {0, 1, 2, 3, 4, 6, 7, 8, 9, 12, 13, 14, 18, 19, 24};
        static const signed char rowB[15] =
            {5, 10, 15, 20, 25, 11, 16, 21, 26, 17, 22, 27, 23, 28, 29};

        float sum = 0.f;
        #pragma unroll
        for (int t = tid; t < 240; t += 32) {
            const int p = t >> 4;
            const int l = t & 15;
            sum += V[rowA[p]][l] * V[rowB[p]][l];
        }
        #pragma unroll
        for (int o = 16; o > 0; o >>= 1)
            sum += __shfl_xor_sync(0xFFFFFFFFu, sum, o);

        if (tid == 0) {
            float lin = bd[0];
            #pragma unroll
            for (int i = 0; i < 6; i++) lin += sfeat[i] * Wd[i];
            lin = fmaxf(lin, 0.f);
            const float z = lin + sum;
            out[b] = 1.0f / (1.0f + __expf(-z));
        }
    }
}

// ---------------- fallback kernel: scalar gathers (known-correct path) ----------------
__global__ __launch_bounds__(128) void ffm_kernel_scalar(
    const int* __restrict__ x0, const int* __restrict__ x1,
    const int* __restrict__ x2, const int* __restrict__ x3,
    const int* __restrict__ x4, const int* __restrict__ x5,
    const float* __restrict__ E0, const float* __restrict__ E1,
    const float* __restrict__ E2, const float* __restrict__ E3,
    const float* __restrict__ E4, const float* __restrict__ E5,
    const float* __restrict__ L0, const float* __restrict__ L1,
    const float* __restrict__ L2t, const float* __restrict__ L3,
    const float* __restrict__ L4, const float* __restrict__ L5,
    const float* __restrict__ Wd, const float* __restrict__ bd,
    float* __restrict__ out)
{
    __shared__ int   sidx[NIDX];
    __shared__ float V[30][16];
    __shared__ float sfeat[6];

    const int b   = blockIdx.x;
    const int tid = threadIdx.x;

    if (tid == 0)      sidx[0]  = x0[b];
    else if (tid == 1) sidx[1]  = x1[b];
    else if (tid == 2) sidx[72] = x4[b];
    else if (tid == 3) sidx[73] = x5[b];
    if (tid >= 4  && tid < 24)  sidx[52 + (tid - 4)]  = x3[b * 20 + (tid - 4)];
    if (tid >= 64 && tid < 114) sidx[2  + (tid - 64)] = x2[b * 50 + (tid - 64)];
    __syncthreads();

    if (tid < 80) {
        const int s = tid >> 4;
        const int l = tid & 15;
        V[0 * 5 + s][l] = E0[(s * 1000000 + sidx[0])  * 16 + l];
        V[1 * 5 + s][l] = E1[(s * 500000  + sidx[1])  * 16 + l];
        V[4 * 5 + s][l] = E4[(s * 10000   + sidx[72]) * 16 + l];
        V[5 * 5 + s][l] = E5[(s * 1000    + sidx[73]) * 16 + l];
        float acc2 = 0.f;
        #pragma unroll
        for (int k = 0; k < 50; k++)
            acc2 += E2[(s * 500000 + sidx[2 + k]) * 16 + l];
        V[2 * 5 + s][l] = acc2 * (1.0f / 50.0f);
        float acc3 = 0.f;
        #pragma unroll
        for (int k = 0; k < 20; k++)
            acc3 += E3[(s * 100000 + sidx[52 + k]) * 16 + l];
        V[3 * 5 + s][l] = acc3 * (1.0f / 20.0f);
    } else if (tid < 86) {
        const int i = tid - 80;
        float f = 0.f;
        switch (i) {
            case 0: f = L0[sidx[0]];  break;
            case 1: f = L1[sidx[1]];  break;
            case 2: {
                float a = 0.f;
                #pragma unroll
                for (int k = 0; k < 50; k++) a += L2t[sidx[2 + k]];
                f = a * (1.0f / 50.0f);
            } break;
            case 3: {
                float a = 0.f;
                #pragma unroll
                for (int k = 0; k < 20; k++) a += L3[sidx[52 + k]];
                f = a * (1.0f / 20.0f);
            } break;
            case 4: f = L4[sidx[72]]; break;
            case 5: f = L5[sidx[73]]; break;
        }
        sfeat[i] = f;
    }
    __syncthreads();

    if (tid < 32) {
        static const signed char rowA[15] =
            {0, 1, 2, 3, 4, 6, 7, 8, 9, 12, 13, 14, 18, 19, 24};
        static const signed char rowB[15] =
            {5, 10, 15, 20, 25, 11, 16, 21, 26, 17, 22, 27, 23, 28, 29};
        float sum = 0.f;
        #pragma unroll
        for (int t = tid; t < 240; t += 32) {
            const int p = t >> 4;
            const int l = t & 15;
            sum += V[rowA[p]][l] * V[rowB[p]][l];
        }
        #pragma unroll
        for (int o = 16; o > 0; o >>= 1)
            sum += __shfl_xor_sync(0xFFFFFFFFu, sum, o);
        if (tid == 0) {
            float lin = bd[0];
            #pragma unroll
            for (int i = 0; i < 6; i++) lin += sfeat[i] * Wd[i];
            lin = fmaxf(lin, 0.f);
            const float z = lin + sum;
            out[b] = 1.0f / (1.0f + __expf(-z));
        }
    }
}

extern "C" void kernel_launch(void* const* d_in, const int* in_sizes, int n_in,
                              void* d_out, int out_size)
{
    const int* x[6];
    for (int i = 0; i < 6; i++) x[i] = (const int*)d_in[i];

    const float *E[6], *L[6], *Wd, *bd;

    // Interleaved (x0..x5, E0,L0,...,E5,L5, Wd, bd) vs flat (x..,E0..E5,L0..L5).
    if (in_sizes[7] == 1000000) {
        for (int i = 0; i < 6; i++) {
            E[i] = (const float*)d_in[6 + 2 * i];
            L[i] = (const float*)d_in[7 + 2 * i];
        }
    } else {
        for (int i = 0; i < 6; i++) {
            E[i] = (const float*)d_in[6 + i];
            L[i] = (const float*)d_in[12 + i];
        }
    }
    Wd = (const float*)d_in[18];
    bd = (const float*)d_in[19];

    float* out = (float*)d_out;
    const int B = out_size;  // 16384

    uintptr_t mis = 0;
    for (int i = 0; i < 6; i++) mis |= (uintptr_t)E[i];
    if ((mis & 15) == 0) {
        ffm_kernel_v8<<<B, 96>>>(x[0], x[1], x[2], x[3], x[4], x[5],
                                 E[0], E[1], E[2], E[3], E[4], E[5],
                                 L[0], L[1], L[2], L[3], L[4], L[5],
                                 Wd, bd, out);
    } else {
        ffm_kernel_scalar<<<B, 128>>>(x[0], x[1], x[2], x[3], x[4], x[5],
                                      E[0], E[1], E[2], E[3], E[4], E[5],
                                      L[0], L[1], L[2], L[3], L[4], L[5],
                                      Wd, bd, out);
    }
}

// round 17
// speedup vs baseline: 1.0913x; 1.0913x over previous
#include <cuda_runtime.h>
#include <cstdint>

// FFM forward: out[b] = sigmoid( relu(sum_i feats[i]*Wd[i] + bd) + fm[b] )
// fm[b] = sum over 15 field pairs (i<j) of dot( mean_k E_i[j-1][x_i[b,k]],
//                                               mean_k E_j[i  ][x_j[b,k]] )
// Shapes: x_i (B,S_i) i32; E_i (5,D_i,16) f32; L_i (D_i,1) f32; Wd (6,1); bd (1,).
// B=16384, S={1,1,50,20,1,1}, D={1e6,5e5,5e5,1e5,1e4,1e3}.
// Inputs interleaved: x0..x5, E0,L0,E1,L1,...,E5,L5, Wd, bd (detected at launch).
//
// L2 policy (L2-ONLY; L1 untouched). L2 persists across graph replays:
//   E2 -> fractional: 25% of accesses evict_last (~40MB probabilistically
//         resident across replays), 75% evict_first. No per-load branch.
//   E3 -> evict_last (32MB table fully resident; the R10 win).
//   E0/E1 -> evict_first (no-reuse streams).
//   Total evict_last demand ~72MB < class capacity (96MB in R15 thrashed).
//
// (R16 was an infra failure — this resubmits the same experiment.)

#define NIDX 74

__device__ __forceinline__ float4 ldg_v4_policy(const float4* p, uint64_t pol) {
    float4 v;
    asm volatile("ld.global.nc.L2::cache_hint.v4.f32 {%0,%1,%2,%3}, [%4], %5;"
                 : "=f"(v.x), "=f"(v.y), "=f"(v.z), "=f"(v.w)
                 : "l"(p), "l"(pol));
    return v;
}

// ---------------- fast kernel: float4 gathers + L2 policies ----------------
__global__ __launch_bounds__(96) void ffm_kernel_v9(
    const int* __restrict__ x0, const int* __restrict__ x1,
    const int* __restrict__ x2, const int* __restrict__ x3,
    const int* __restrict__ x4, const int* __restrict__ x5,
    const float* __restrict__ E0, const float* __restrict__ E1,
    const float* __restrict__ E2, const float* __restrict__ E3,
    const float* __restrict__ E4, const float* __restrict__ E5,
    const float* __restrict__ L0, const float* __restrict__ L1,
    const float* __restrict__ L2t, const float* __restrict__ L3,
    const float* __restrict__ L4, const float* __restrict__ L5,
    const float* __restrict__ Wd, const float* __restrict__ bd,
    float* __restrict__ out)
{
    __shared__ __align__(16) float V[30][16];  // (feature*5 + slot, latent)
    __shared__ int   sidx[NIDX];   // [0]=x0 [1]=x1 [2..51]=x2 [52..71]=x3 [72]=x4 [73]=x5
    __shared__ float sfeat[6];

    const int b   = blockIdx.x;
    const int tid = threadIdx.x;

    // ---- load indices into smem ----
    if (tid < 50)                  sidx[2  + tid]        = x2[b * 50 + tid];
    else if (tid < 70)             sidx[52 + (tid - 50)] = x3[b * 20 + (tid - 50)];
    else if (tid == 70)            sidx[0]  = x0[b];
    else if (tid == 71)            sidx[1]  = x1[b];
    else if (tid == 72)            sidx[72] = x4[b];
    else if (tid == 73)            sidx[73] = x5[b];
    __syncthreads();

    // ---- gather: 80 threads = (slot s 0..4) x (quad q 0..3) x (ksub 0..3) ----
    if (tid < 80) {
        const int s    = tid >> 4;        // slot
        const int q    = (tid >> 2) & 3;  // float4 quad within row
        const int ksub = tid & 3;         // k-parallel split / singleton select
        const unsigned mask = (tid < 64) ? 0xFFFFFFFFu : 0x0000FFFFu;

        uint64_t pol_first, pol_last, pol_e2;
        asm volatile("createpolicy.fractional.L2::evict_first.b64 %0, 1.0;" : "=l"(pol_first));
        asm volatile("createpolicy.fractional.L2::evict_last.b64  %0, 1.0;" : "=l"(pol_last));
        asm volatile("createpolicy.fractional.L2::evict_last.L2::evict_first.b64 %0, 0.25;"
                     : "=l"(pol_e2));

        // feature 2: 50 indices split 4 ways; fractional 25% evict_last
        float4 a2 = make_float4(0.f, 0.f, 0.f, 0.f);
        #pragma unroll
        for (int k = ksub; k < 50; k += 4) {
            const int row = s * 500000 + sidx[2 + k];
            const float4 v = ldg_v4_policy((const float4*)E2 + (long)row * 4 + q, pol_e2);
            a2.x += v.x; a2.y += v.y; a2.z += v.z; a2.w += v.w;
        }

        // feature 3: 20 indices split 4 ways; L2 evict-last (32MB resident)
        float4 a3 = make_float4(0.f, 0.f, 0.f, 0.f);
        #pragma unroll
        for (int k = ksub; k < 20; k += 4) {
            const int row = s * 100000 + sidx[52 + k];
            const float4 v = ldg_v4_policy((const float4*)E3 + (long)row * 4 + q, pol_last);
            a3.x += v.x; a3.y += v.y; a3.z += v.z; a3.w += v.w;
        }

        // singleton features: ksub 0->E0, 1->E1 (evict-first), 2->E4, 3->E5 (default)
        {
            float4 v;
            int frow;
            if (ksub == 0) {
                v = ldg_v4_policy((const float4*)E0 + (long)(s * 1000000 + sidx[0]) * 4 + q, pol_first);
                frow = 0 * 5 + s;
            } else if (ksub == 1) {
                v = ldg_v4_policy((const float4*)E1 + (long)(s * 500000 + sidx[1]) * 4 + q, pol_first);
                frow = 1 * 5 + s;
            } else if (ksub == 2) {
                v = __ldg((const float4*)E4 + (long)(s * 10000 + sidx[72]) * 4 + q);
                frow = 4 * 5 + s;
            } else {
                v = __ldg((const float4*)E5 + (long)(s * 1000 + sidx[73]) * 4 + q);
                frow = 5 * 5 + s;
            }
            ((float4*)&V[frow][0])[q] = v;
        }

        // reduce seq partials across the 4 ksub lanes
        #pragma unroll
        for (int o = 1; o <= 2; o <<= 1) {
            a2.x += __shfl_xor_sync(mask, a2.x, o);
            a2.y += __shfl_xor_sync(mask, a2.y, o);
            a2.z += __shfl_xor_sync(mask, a2.z, o);
            a2.w += __shfl_xor_sync(mask, a2.w, o);
            a3.x += __shfl_xor_sync(mask, a3.x, o);
            a3.y += __shfl_xor_sync(mask, a3.y, o);
            a3.z += __shfl_xor_sync(mask, a3.z, o);
            a3.w += __shfl_xor_sync(mask, a3.w, o);
        }
        if (ksub == 0) {
            const float i50 = 1.0f / 50.0f, i20 = 1.0f / 20.0f;
            ((float4*)&V[2 * 5 + s][0])[q] =
                make_float4(a2.x * i50, a2.y * i50, a2.z * i50, a2.w * i50);
            ((float4*)&V[3 * 5 + s][0])[q] =
                make_float4(a3.x * i20, a3.y * i20, a3.z * i20, a3.w * i20);
        }
    } else if (tid < 86) {
        // ---- linear features (small tables, default policy) ----
        const int i = tid - 80;
        float f = 0.f;
        switch (i) {
            case 0: f = L0[sidx[0]];  break;
            case 1: f = L1[sidx[1]];  break;
            case 2: {
                float a = 0.f;
                #pragma unroll
                for (int k = 0; k < 50; k++) a += L2t[sidx[2 + k]];
                f = a * (1.0f / 50.0f);
            } break;
            case 3: {
                float a = 0.f;
                #pragma unroll
                for (int k = 0; k < 20; k++) a += L3[sidx[52 + k]];
                f = a * (1.0f / 20.0f);
            } break;
            case 4: f = L4[sidx[72]]; break;
            case 5: f = L5[sidx[73]]; break;
        }
        sfeat[i] = f;
    }
    __syncthreads();

    // ---- fm: 15 disjoint pair dot-products over 16 lanes each ----
    if (tid < 32) {
        static const signed char rowA[15] =
            {0, 1, 2, 3, 4, 6, 7, 8, 9, 12, 13, 14, 18, 19, 24};
        static const signed char rowB[15] =
            {5, 10, 15, 20, 25, 11, 16, 21, 26, 17, 22, 27, 23, 28, 29};

        float sum = 0.f;
        #pragma unroll
        for (int t = tid; t < 240; t += 32) {
            const int p = t >> 4;
            const int l = t & 15;
            sum += V[rowA[p]][l] * V[rowB[p]][l];
        }
        #pragma unroll
        for (int o = 16; o > 0; o >>= 1)
            sum += __shfl_xor_sync(0xFFFFFFFFu, sum, o);

        if (tid == 0) {
            float lin = bd[0];
            #pragma unroll
            for (int i = 0; i < 6; i++) lin += sfeat[i] * Wd[i];
            lin = fmaxf(lin, 0.f);
            const float z = lin + sum;
            out[b] = 1.0f / (1.0f + __expf(-z));
        }
    }
}

// ---------------- fallback kernel: scalar gathers (known-correct path) ----------------
__global__ __launch_bounds__(128) void ffm_kernel_scalar(
    const int* __restrict__ x0, const int* __restrict__ x1,
    const int* __restrict__ x2, const int* __restrict__ x3,
    const int* __restrict__ x4, const int* __restrict__ x5,
    const float* __restrict__ E0, const float* __restrict__ E1,
    const float* __restrict__ E2, const float* __restrict__ E3,
    const float* __restrict__ E4, const float* __restrict__ E5,
    const float* __restrict__ L0, const float* __restrict__ L1,
    const float* __restrict__ L2t, const float* __restrict__ L3,
    const float* __restrict__ L4, const float* __restrict__ L5,
    const float* __restrict__ Wd, const float* __restrict__ bd,
    float* __restrict__ out)
{
    __shared__ int   sidx[NIDX];
    __shared__ float V[30][16];
    __shared__ float sfeat[6];

    const int b   = blockIdx.x;
    const int tid = threadIdx.x;

    if (tid == 0)      sidx[0]  = x0[b];
    else if (tid == 1) sidx[1]  = x1[b];
    else if (tid == 2) sidx[72] = x4[b];
    else if (tid == 3) sidx[73] = x5[b];
    if (tid >= 4  && tid < 24)  sidx[52 + (tid - 4)]  = x3[b * 20 + (tid - 4)];
    if (tid >= 64 && tid < 114) sidx[2  + (tid - 64)] = x2[b * 50 + (tid - 64)];
    __syncthreads();

    if (tid < 80) {
        const int s = tid >> 4;
        const int l = tid & 15;
        V[0 * 5 + s][l] = E0[(s * 1000000 + sidx[0])  * 16 + l];
        V[1 * 5 + s][l] = E1[(s * 500000  + sidx[1])  * 16 + l];
        V[4 * 5 + s][l] = E4[(s * 10000   + sidx[72]) * 16 + l];
        V[5 * 5 + s][l] = E5[(s * 1000    + sidx[73]) * 16 + l];
        float acc2 = 0.f;
        #pragma unroll
        for (int k = 0; k < 50; k++)
            acc2 += E2[(s * 500000 + sidx[2 + k]) * 16 + l];
        V[2 * 5 + s][l] = acc2 * (1.0f / 50.0f);
        float acc3 = 0.f;
        #pragma unroll
        for (int k = 0; k < 20; k++)
            acc3 += E3[(s * 100000 + sidx[52 + k]) * 16 + l];
        V[3 * 5 + s][l] = acc3 * (1.0f / 20.0f);
    } else if (tid < 86) {
        const int i = tid - 80;
        float f = 0.f;
        switch (i) {
            case 0: f = L0[sidx[0]];  break;
            case 1: f = L1[sidx[1]];  break;
            case 2: {
                float a = 0.f;
                #pragma unroll
                for (int k = 0; k < 50; k++) a += L2t[sidx[2 + k]];
                f = a * (1.0f / 50.0f);
            } break;
            case 3: {
                float a = 0.f;
                #pragma unroll
                for (int k = 0; k < 20; k++) a += L3[sidx[52 + k]];
                f = a * (1.0f / 20.0f);
            } break;
            case 4: f = L4[sidx[72]]; break;
            case 5: f = L5[sidx[73]]; break;
        }
        sfeat[i] = f;
    }
    __syncthreads();

    if (tid < 32) {
        static const signed char rowA[15] =
            {0, 1, 2, 3, 4, 6, 7, 8, 9, 12, 13, 14, 18, 19, 24};
        static const signed char rowB[15] =
            {5, 10, 15, 20, 25, 11, 16, 21, 26, 17, 22, 27, 23, 28, 29};
        float sum = 0.f;
        #pragma unroll
        for (int t = tid; t < 240; t += 32) {
            const int p = t >> 4;
            const int l = t & 15;
            sum += V[rowA[p]][l] * V[rowB[p]][l];
        }
        #pragma unroll
        for (int o = 16; o > 0; o >>= 1)
            sum += __shfl_xor_sync(0xFFFFFFFFu, sum, o);
        if (tid == 0) {
            float lin = bd[0];
            #pragma unroll
            for (int i = 0; i < 6; i++) lin += sfeat[i] * Wd[i];
            lin = fmaxf(lin, 0.f);
            const float z = lin + sum;
            out[b] = 1.0f / (1.0f + __expf(-z));
        }
    }
}

extern "C" void kernel_launch(void* const* d_in, const int* in_sizes, int n_in,
                              void* d_out, int out_size)
{
    const int* x[6];
    for (int i = 0; i < 6; i++) x[i] = (const int*)d_in[i];

    const float *E[6], *L[6], *Wd, *bd;

    // Interleaved (x0..x5, E0,L0,...,E5,L5, Wd, bd) vs flat (x..,E0..E5,L0..L5).
    if (in_sizes[7] == 1000000) {
        for (int i = 0; i < 6; i++) {
            E[i] = (const float*)d_in[6 + 2 * i];
            L[i] = (const float*)d_in[7 + 2 * i];
        }
    } else {
        for (int i = 0; i < 6; i++) {
            E[i] = (const float*)d_in[6 + i];
            L[i] = (const float*)d_in[12 + i];
        }
    }
    Wd = (const float*)d_in[18];
    bd = (const float*)d_in[19];

    float* out = (float*)d_out;
    const int B = out_size;  // 16384

    uintptr_t mis = 0;
    for (int i = 0; i < 6; i++) mis |= (uintptr_t)E[i];
    if ((mis & 15) == 0) {
        ffm_kernel_v9<<<B, 96>>>(x[0], x[1], x[2], x[3], x[4], x[5],
                                 E[0], E[1], E[2], E[3], E[4], E[5],
                                 L[0], L[1], L[2], L[3], L[4], L[5],
                                 Wd, bd, out);
    } else {
        ffm_kernel_scalar<<<B, 128>>>(x[0], x[1], x[2], x[3], x[4], x[5],
                                      E[0], E[1], E[2], E[3], E[4], E[5],
                                      L[0], L[1], L[2], L[3], L[4], L[5],
                                      Wd, bd, out);
    }
}